// round 1
// baseline (speedup 1.0000x reference)
#include <cuda_runtime.h>

#define B_  4
#define T_  2048
#define D_  1024
#define H_  16
#define DK_ 64
#define M_  (B_*T_)

// Scratch (allocation-free rule: module-scope device globals)
__device__ float g_qkv[(size_t)M_ * 3 * D_];   // [B,T,3D]
__device__ float g_att[(size_t)M_ * D_];       // [B,T,D] attention output (pre out-proj)

// ---------------------------------------------------------------------------
// SGEMM with bias: C[M,N] = A[M,K] @ B[K,N] + bias[N]
// 128x128 tile, BK=8, 256 threads, 8x8 per thread.
// ---------------------------------------------------------------------------
__global__ __launch_bounds__(256)
void sgemm_bias_kernel(const float* __restrict__ A, const float* __restrict__ Bm,
                       const float* __restrict__ bias, float* __restrict__ C,
                       int M, int N, int K)
{
    __shared__ float As[8][128];   // transposed A tile: As[k][m]
    __shared__ float Bs[8][128];   // Bs[k][n]

    const int tid = threadIdx.x;
    const int m0 = blockIdx.y * 128;
    const int n0 = blockIdx.x * 128;
    const int tm = (tid >> 4) * 8;     // thread row base within tile
    const int tn = (tid & 15) * 8;     // thread col base within tile

    const int arow = tid >> 1;         // 0..127
    const int acol = (tid & 1) * 4;    // 0 or 4
    const int brow = tid >> 5;         // 0..7
    const int bcol = (tid & 31) * 4;   // 0..124

    float acc[8][8];
#pragma unroll
    for (int i = 0; i < 8; i++)
#pragma unroll
        for (int j = 0; j < 8; j++) acc[i][j] = 0.f;

    const float* Aptr = A + (size_t)(m0 + arow) * K + acol;
    const float* Bptr = Bm + (size_t)brow * N + n0 + bcol;

    for (int k0 = 0; k0 < K; k0 += 8) {
        float4 a4 = *(const float4*)(Aptr + k0);
        As[acol + 0][arow] = a4.x;
        As[acol + 1][arow] = a4.y;
        As[acol + 2][arow] = a4.z;
        As[acol + 3][arow] = a4.w;
        float4 b4 = *(const float4*)(Bptr + (size_t)k0 * N);
        *(float4*)&Bs[brow][bcol] = b4;
        __syncthreads();

#pragma unroll
        for (int k = 0; k < 8; k++) {
            float ra[8], rb[8];
            *(float4*)&ra[0] = *(const float4*)&As[k][tm];
            *(float4*)&ra[4] = *(const float4*)&As[k][tm + 4];
            *(float4*)&rb[0] = *(const float4*)&Bs[k][tn];
            *(float4*)&rb[4] = *(const float4*)&Bs[k][tn + 4];
#pragma unroll
            for (int i = 0; i < 8; i++)
#pragma unroll
                for (int j = 0; j < 8; j++)
                    acc[i][j] += ra[i] * rb[j];
        }
        __syncthreads();
    }

    float bv[8];
#pragma unroll
    for (int j = 0; j < 8; j++) bv[j] = bias[n0 + tn + j];

#pragma unroll
    for (int i = 0; i < 8; i++) {
        float* crow = C + (size_t)(m0 + tm + i) * N + n0 + tn;
        float4 v0, v1;
        v0.x = acc[i][0] + bv[0]; v0.y = acc[i][1] + bv[1];
        v0.z = acc[i][2] + bv[2]; v0.w = acc[i][3] + bv[3];
        v1.x = acc[i][4] + bv[4]; v1.y = acc[i][5] + bv[5];
        v1.z = acc[i][6] + bv[6]; v1.w = acc[i][7] + bv[7];
        *(float4*)(crow)     = v0;
        *(float4*)(crow + 4) = v1;
    }
}

// ---------------------------------------------------------------------------
// Flash attention (fp32, causal). One block = 64 queries of one (b,h).
// Online softmax; two 64x64x64 register-tiled micro-GEMMs per kv tile.
// Dynamic smem layout (row stride 68 floats so float4 rows stay 16B-aligned):
//   Qt[d][q], Kt[d][kv], Vs[kv][d], Ss[q][kv], Pt[kv][q], m/l/alpha[64]
// ---------------------------------------------------------------------------
#define LD_ 68
#define FLASH_SMEM ((5 * 64 * LD_ + 3 * 64) * 4)

__global__ __launch_bounds__(256)
void flash_attn_kernel(const float* __restrict__ qkv, float* __restrict__ out)
{
    extern __shared__ float sm[];
    float* Qt   = sm;                 // [64][LD_]  Qt[d][q]
    float* Kt   = Qt + 64 * LD_;      // Kt[d][kv]
    float* Vs   = Kt + 64 * LD_;      // Vs[kv][d]
    float* Ss   = Vs + 64 * LD_;      // Ss[q][kv]
    float* Pt   = Ss + 64 * LD_;      // Pt[kv][q]
    float* m_s  = Pt + 64 * LD_;
    float* l_s  = m_s + 64;
    float* al_s = l_s + 64;

    const int tid = threadIdx.x;
    const int tx = tid & 15;          // 0..15 (cols)
    const int ty = tid >> 4;          // 0..15 (rows)
    const int bh = blockIdx.y;
    const int b  = bh >> 4;
    const int h  = bh & 15;
    const int q0 = blockIdx.x * 64;

    const size_t rs = (size_t)3 * D_;                       // row stride of qkv
    const float* base = qkv + (size_t)b * T_ * rs + h * DK_;

    // Load Q tile, transposed: Qt[d][q]
    {
        const int r  = tid >> 4;          // 0..15
        const int d4 = (tid & 15) * 4;
#pragma unroll
        for (int l = 0; l < 4; l++) {
            int row = r + l * 16;
            float4 v = *(const float4*)(base + (size_t)(q0 + row) * rs + d4);
            Qt[(d4 + 0) * LD_ + row] = v.x;
            Qt[(d4 + 1) * LD_ + row] = v.y;
            Qt[(d4 + 2) * LD_ + row] = v.z;
            Qt[(d4 + 3) * LD_ + row] = v.w;
        }
    }
    if (tid < 64) { m_s[tid] = -3.0e38f; l_s[tid] = 0.f; }

    float o[4][4];
#pragma unroll
    for (int i = 0; i < 4; i++)
#pragma unroll
        for (int j = 0; j < 4; j++) o[i][j] = 0.f;

    const int ntiles = blockIdx.x + 1;
    for (int t = 0; t < ntiles; t++) {
        const int kv0 = t * 64;
        __syncthreads();  // previous iter's consumers of Kt/Vs/Pt done

        // Load K (transposed) and V tiles
        {
            const int r  = tid >> 4;
            const int d4 = (tid & 15) * 4;
#pragma unroll
            for (int l = 0; l < 4; l++) {
                int row = r + l * 16;
                const float* kb = base + (size_t)(kv0 + row) * rs + D_;
                float4 k4 = *(const float4*)(kb + d4);
                Kt[(d4 + 0) * LD_ + row] = k4.x;
                Kt[(d4 + 1) * LD_ + row] = k4.y;
                Kt[(d4 + 2) * LD_ + row] = k4.z;
                Kt[(d4 + 3) * LD_ + row] = k4.w;
                float4 v4 = *(const float4*)(kb + D_ + d4);
                *(float4*)&Vs[row * LD_ + d4] = v4;
            }
        }
        __syncthreads();

        // S = (Q @ K^T) * rsqrt(DK)
        float s[4][4];
#pragma unroll
        for (int i = 0; i < 4; i++)
#pragma unroll
            for (int j = 0; j < 4; j++) s[i][j] = 0.f;

        for (int d = 0; d < 64; d++) {
            float4 qa = *(const float4*)&Qt[d * LD_ + ty * 4];
            float4 kb = *(const float4*)&Kt[d * LD_ + tx * 4];
            float ra[4] = {qa.x, qa.y, qa.z, qa.w};
            float rb[4] = {kb.x, kb.y, kb.z, kb.w};
#pragma unroll
            for (int i = 0; i < 4; i++)
#pragma unroll
                for (int j = 0; j < 4; j++)
                    s[i][j] += ra[i] * rb[j];
        }

        const bool diag = (kv0 == q0);
#pragma unroll
        for (int i = 0; i < 4; i++) {
            int qi = ty * 4 + i;
            float4 v;
            float vv[4];
#pragma unroll
            for (int j = 0; j < 4; j++) {
                int kj = tx * 4 + j;
                float sv = s[i][j] * 0.125f;   // 1/sqrt(64)
                if (diag && kj > qi) sv = -1.0e30f;
                vv[j] = sv;
            }
            v.x = vv[0]; v.y = vv[1]; v.z = vv[2]; v.w = vv[3];
            *(float4*)&Ss[qi * LD_ + tx * 4] = v;
        }
        __syncthreads();

        // Online softmax: one thread per query row
        if (tid < 64) {
            const int r = tid;
            const float4* srow = (const float4*)&Ss[r * LD_];
            float mold = m_s[r];
            float mt = mold;
#pragma unroll
            for (int j = 0; j < 16; j++) {
                float4 v = srow[j];
                mt = fmaxf(mt, fmaxf(fmaxf(v.x, v.y), fmaxf(v.z, v.w)));
            }
            float alpha = __expf(mold - mt);
            float sum = 0.f;
#pragma unroll
            for (int j = 0; j < 16; j++) {
                float4 v = srow[j];
                float p0 = __expf(v.x - mt);
                float p1 = __expf(v.y - mt);
                float p2 = __expf(v.z - mt);
                float p3 = __expf(v.w - mt);
                Pt[(4 * j + 0) * LD_ + r] = p0;
                Pt[(4 * j + 1) * LD_ + r] = p1;
                Pt[(4 * j + 2) * LD_ + r] = p2;
                Pt[(4 * j + 3) * LD_ + r] = p3;
                sum += p0 + p1 + p2 + p3;
            }
            m_s[r]  = mt;
            l_s[r]  = l_s[r] * alpha + sum;
            al_s[r] = alpha;
        }
        __syncthreads();

        // O = O * alpha + P @ V
        float a[4];
#pragma unroll
        for (int i = 0; i < 4; i++) a[i] = al_s[ty * 4 + i];
#pragma unroll
        for (int i = 0; i < 4; i++)
#pragma unroll
            for (int j = 0; j < 4; j++) o[i][j] *= a[i];

        for (int kv = 0; kv < 64; kv++) {
            float4 pa = *(const float4*)&Pt[kv * LD_ + ty * 4];
            float4 vb = *(const float4*)&Vs[kv * LD_ + tx * 4];
            float ra[4] = {pa.x, pa.y, pa.z, pa.w};
            float rb[4] = {vb.x, vb.y, vb.z, vb.w};
#pragma unroll
            for (int i = 0; i < 4; i++)
#pragma unroll
                for (int j = 0; j < 4; j++)
                    o[i][j] += ra[i] * rb[j];
        }
    }

    // Normalize and write out[b, q, h*64 + d]
    float inv[4];
#pragma unroll
    for (int i = 0; i < 4; i++) inv[i] = 1.0f / l_s[ty * 4 + i];
#pragma unroll
    for (int i = 0; i < 4; i++) {
        float4 v;
        v.x = o[i][0] * inv[i];
        v.y = o[i][1] * inv[i];
        v.z = o[i][2] * inv[i];
        v.w = o[i][3] * inv[i];
        size_t off = (size_t)(b * T_ + q0 + ty * 4 + i) * D_ + h * DK_ + tx * 4;
        *(float4*)(out + off) = v;
    }
}

// ---------------------------------------------------------------------------
extern "C" void kernel_launch(void* const* d_in, const int* in_sizes, int n_in,
                              void* d_out, int out_size)
{
    (void)in_sizes; (void)n_in; (void)out_size;
    const float* x     = (const float*)d_in[0];
    const float* W_qkv = (const float*)d_in[1];
    const float* b_qkv = (const float*)d_in[2];
    const float* W_out = (const float*)d_in[3];
    const float* b_out = (const float*)d_in[4];
    float* out = (float*)d_out;

    float *qkv_ptr = nullptr, *att_ptr = nullptr;
    cudaGetSymbolAddress((void**)&qkv_ptr, g_qkv);
    cudaGetSymbolAddress((void**)&att_ptr, g_att);

    cudaFuncSetAttribute(flash_attn_kernel,
                         cudaFuncAttributeMaxDynamicSharedMemorySize, FLASH_SMEM);

    // 1) QKV projection: [8192,1024] @ [1024,3072] + b
    dim3 g1(3 * D_ / 128, M_ / 128);
    sgemm_bias_kernel<<<g1, 256>>>(x, W_qkv, b_qkv, qkv_ptr, M_, 3 * D_, D_);

    // 2) Causal attention
    dim3 g2(T_ / 64, B_ * H_);
    flash_attn_kernel<<<g2, 256, FLASH_SMEM>>>(qkv_ptr, att_ptr);

    // 3) Output projection: [8192,1024] @ [1024,1024] + b
    dim3 g3(D_ / 128, M_ / 128);
    sgemm_bias_kernel<<<g3, 256>>>(att_ptr, W_out, b_out, out, M_, D_, D_);
}

// round 3
// speedup vs baseline: 1.6688x; 1.6688x over previous
#include <cuda_runtime.h>
#include <cstdint>

#define B_  4
#define T_  2048
#define D_  1024
#define H_  16
#define DK_ 64
#define M_  (B_*T_)

// Scratch (allocation-free rule: module-scope device globals)
__device__ float g_qkv[(size_t)M_ * 3 * D_];     // [B,T,3D]
__device__ float g_att[(size_t)M_ * D_];         // [B,T,D]
__device__ float g_wqkv_t[(size_t)3 * D_ * D_];  // W_qkv^T [3D, D]
__device__ float g_wout_t[(size_t)D_ * D_];      // W_out^T [D, D]

// ---------------------------------------------------------------------------
// Transpose: out[c][r] = in[r][c]   (in: [R,C])
// ---------------------------------------------------------------------------
__global__ __launch_bounds__(256)
void transpose_kernel(const float* __restrict__ in, float* __restrict__ out,
                      int R, int C)
{
    __shared__ float t[32][33];
    int bx = blockIdx.x * 32;   // C offset
    int by = blockIdx.y * 32;   // R offset
    int tx = threadIdx.x & 31, ty = threadIdx.x >> 5;
#pragma unroll
    for (int j = 0; j < 32; j += 8)
        t[ty + j][tx] = in[(size_t)(by + ty + j) * C + bx + tx];
    __syncthreads();
#pragma unroll
    for (int j = 0; j < 32; j += 8)
        out[(size_t)(bx + ty + j) * R + by + tx] = t[tx][ty + j];
}

// ---------------------------------------------------------------------------
// tf32 mma.sync GEMM: C[M,N] = A[M,K] @ Bt[N,K]^T + bias[N]
// CTA tile 128x128, BK=16, 8 warps (2 along M x 4 along N), warp tile 64x32.
// Each warp: 4 m16 tiles x 4 n8 tiles of m16n8k8 tf32 mma.
// Smem [row][20] padding: row*20 mod 32 = {0,20,8,28,16,4,24,12} for 8 rows,
// + k(0..3) -> 32 distinct banks for the (grp,tg) fragment pattern.
// ---------------------------------------------------------------------------
#define APAD   20
#define TILE_B (128 * APAD * 4)          // one operand tile: 10240 B
#define STAGE_B (2 * TILE_B)             // A + B tiles: 20480 B
#define GEMM_SMEM (2 * STAGE_B)          // double buffered: 40960 B

__device__ __forceinline__ void cvt4_rna(uint32_t (&o)[4], float4 v) {
    asm("cvt.rna.tf32.f32 %0, %1;" : "=r"(o[0]) : "f"(v.x));
    asm("cvt.rna.tf32.f32 %0, %1;" : "=r"(o[1]) : "f"(v.y));
    asm("cvt.rna.tf32.f32 %0, %1;" : "=r"(o[2]) : "f"(v.z));
    asm("cvt.rna.tf32.f32 %0, %1;" : "=r"(o[3]) : "f"(v.w));
}

__device__ __forceinline__ void mma_tf32(float (&c)[4], const uint32_t (&a)[4],
                                         const uint32_t (&b)[2]) {
    asm volatile(
        "mma.sync.aligned.m16n8k8.row.col.f32.tf32.tf32.f32 "
        "{%0,%1,%2,%3}, {%4,%5,%6,%7}, {%8,%9}, {%0,%1,%2,%3};"
        : "+f"(c[0]), "+f"(c[1]), "+f"(c[2]), "+f"(c[3])
        : "r"(a[0]), "r"(a[1]), "r"(a[2]), "r"(a[3]), "r"(b[0]), "r"(b[1]));
}

__global__ __launch_bounds__(256, 2)
void gemm_tf32_kernel(const float* __restrict__ A,   // [M,K]
                      const float* __restrict__ Bt,  // [N,K]
                      const float* __restrict__ bias,
                      float* __restrict__ C,
                      int M, int N, int K)
{
    extern __shared__ char smem[];
    const int tid  = threadIdx.x;
    const int wid  = tid >> 5;
    const int lane = tid & 31;
    const int grp  = lane >> 2;      // 0..7
    const int tg   = lane & 3;       // 0..3
    const int warp_m = (wid & 1) * 64;
    const int warp_n = (wid >> 1) * 32;
    const int m0 = blockIdx.y * 128;
    const int n0 = blockIdx.x * 128;
    const int nk = K >> 4;           // chunks of BK=16

    // loader indices: 2 float4 per thread per operand; idx -> (row, kcol)
    const int r0 = (tid) >> 2,        kc0 = ((tid) & 3) << 2;
    const int r1 = (tid + 256) >> 2,  kc1 = ((tid + 256) & 3) << 2;

    const float* Abase = A + (size_t)m0 * K;
    const float* Bbase = Bt + (size_t)n0 * K;

    float acc[4][4][4];
#pragma unroll
    for (int i = 0; i < 4; i++)
#pragma unroll
        for (int j = 0; j < 4; j++)
#pragma unroll
            for (int r = 0; r < 4; r++) acc[i][j][r] = 0.f;

    float4 ra0, ra1, rb0, rb1;
    ra0 = *(const float4*)(Abase + (size_t)r0 * K + kc0);
    ra1 = *(const float4*)(Abase + (size_t)r1 * K + kc1);
    rb0 = *(const float4*)(Bbase + (size_t)r0 * K + kc0);
    rb1 = *(const float4*)(Bbase + (size_t)r1 * K + kc1);

    for (int i = 0; i < nk; i++) {
        float* As = (float*)(smem + (i & 1) * STAGE_B);
        float* Bs = (float*)(smem + (i & 1) * STAGE_B + TILE_B);

        {   // STS with rna->tf32 conversion
            uint32_t c4[4];
            cvt4_rna(c4, ra0); *(uint4*)(As + r0 * APAD + kc0) = *(uint4*)c4;
            cvt4_rna(c4, ra1); *(uint4*)(As + r1 * APAD + kc1) = *(uint4*)c4;
            cvt4_rna(c4, rb0); *(uint4*)(Bs + r0 * APAD + kc0) = *(uint4*)c4;
            cvt4_rna(c4, rb1); *(uint4*)(Bs + r1 * APAD + kc1) = *(uint4*)c4;
        }
        __syncthreads();

        if (i + 1 < nk) {
            const int k0 = (i + 1) << 4;
            ra0 = *(const float4*)(Abase + (size_t)r0 * K + k0 + kc0);
            ra1 = *(const float4*)(Abase + (size_t)r1 * K + k0 + kc1);
            rb0 = *(const float4*)(Bbase + (size_t)r0 * K + k0 + kc0);
            rb1 = *(const float4*)(Bbase + (size_t)r1 * K + k0 + kc1);
        }

        const uint32_t* Au = (const uint32_t*)As;
        const uint32_t* Bu = (const uint32_t*)Bs;
#pragma unroll
        for (int ks = 0; ks < 2; ks++) {
            const int k0 = ks * 8 + tg;
            uint32_t a[4][4];
#pragma unroll
            for (int ii = 0; ii < 4; ii++) {
                const uint32_t* p0 = Au + (warp_m + 16 * ii + grp) * APAD;
                a[ii][0] = p0[k0];
                a[ii][2] = p0[k0 + 4];
                const uint32_t* p1 = p0 + 8 * APAD;
                a[ii][1] = p1[k0];
                a[ii][3] = p1[k0 + 4];
            }
            uint32_t b[4][2];
#pragma unroll
            for (int jj = 0; jj < 4; jj++) {
                const uint32_t* pn = Bu + (warp_n + 8 * jj + grp) * APAD;
                b[jj][0] = pn[k0];
                b[jj][1] = pn[k0 + 4];
            }
#pragma unroll
            for (int ii = 0; ii < 4; ii++)
#pragma unroll
                for (int jj = 0; jj < 4; jj++)
                    mma_tf32(acc[ii][jj], a[ii], b[jj]);
        }
    }

    // Epilogue: c0 (grp, 2tg), c1 (grp, 2tg+1), c2 (grp+8, 2tg), c3 (grp+8, 2tg+1)
#pragma unroll
    for (int ii = 0; ii < 4; ii++) {
        const int m = m0 + warp_m + 16 * ii + grp;
#pragma unroll
        for (int jj = 0; jj < 4; jj++) {
            const int n = n0 + warp_n + 8 * jj + 2 * tg;
            const float bv0 = __ldg(&bias[n]);
            const float bv1 = __ldg(&bias[n + 1]);
            float2 v0 = {acc[ii][jj][0] + bv0, acc[ii][jj][1] + bv1};
            float2 v1 = {acc[ii][jj][2] + bv0, acc[ii][jj][3] + bv1};
            *(float2*)(C + (size_t)m * N + n)       = v0;
            *(float2*)(C + (size_t)(m + 8) * N + n) = v1;
        }
    }
}

// ---------------------------------------------------------------------------
// Flash attention (fp32, causal) — unchanged (proven in round 1).
// ---------------------------------------------------------------------------
#define LD_ 68
#define FLASH_SMEM ((5 * 64 * LD_ + 3 * 64) * 4)

__global__ __launch_bounds__(256)
void flash_attn_kernel(const float* __restrict__ qkv, float* __restrict__ out)
{
    extern __shared__ float sm[];
    float* Qt   = sm;
    float* Kt   = Qt + 64 * LD_;
    float* Vs   = Kt + 64 * LD_;
    float* Ss   = Vs + 64 * LD_;
    float* Pt   = Ss + 64 * LD_;
    float* m_s  = Pt + 64 * LD_;
    float* l_s  = m_s + 64;
    float* al_s = l_s + 64;

    const int tid = threadIdx.x;
    const int tx = tid & 15;
    const int ty = tid >> 4;
    const int bh = blockIdx.y;
    const int b  = bh >> 4;
    const int h  = bh & 15;
    const int q0 = blockIdx.x * 64;

    const size_t rs = (size_t)3 * D_;
    const float* base = qkv + (size_t)b * T_ * rs + h * DK_;

    {
        const int r  = tid >> 4;
        const int d4 = (tid & 15) * 4;
#pragma unroll
        for (int l = 0; l < 4; l++) {
            int row = r + l * 16;
            float4 v = *(const float4*)(base + (size_t)(q0 + row) * rs + d4);
            Qt[(d4 + 0) * LD_ + row] = v.x;
            Qt[(d4 + 1) * LD_ + row] = v.y;
            Qt[(d4 + 2) * LD_ + row] = v.z;
            Qt[(d4 + 3) * LD_ + row] = v.w;
        }
    }
    if (tid < 64) { m_s[tid] = -3.0e38f; l_s[tid] = 0.f; }

    float o[4][4];
#pragma unroll
    for (int i = 0; i < 4; i++)
#pragma unroll
        for (int j = 0; j < 4; j++) o[i][j] = 0.f;

    const int ntiles = blockIdx.x + 1;
    for (int t = 0; t < ntiles; t++) {
        const int kv0 = t * 64;
        __syncthreads();

        {
            const int r  = tid >> 4;
            const int d4 = (tid & 15) * 4;
#pragma unroll
            for (int l = 0; l < 4; l++) {
                int row = r + l * 16;
                const float* kb = base + (size_t)(kv0 + row) * rs + D_;
                float4 k4 = *(const float4*)(kb + d4);
                Kt[(d4 + 0) * LD_ + row] = k4.x;
                Kt[(d4 + 1) * LD_ + row] = k4.y;
                Kt[(d4 + 2) * LD_ + row] = k4.z;
                Kt[(d4 + 3) * LD_ + row] = k4.w;
                float4 v4 = *(const float4*)(kb + D_ + d4);
                *(float4*)&Vs[row * LD_ + d4] = v4;
            }
        }
        __syncthreads();

        float s[4][4];
#pragma unroll
        for (int i = 0; i < 4; i++)
#pragma unroll
            for (int j = 0; j < 4; j++) s[i][j] = 0.f;

        for (int d = 0; d < 64; d++) {
            float4 qa = *(const float4*)&Qt[d * LD_ + ty * 4];
            float4 kb = *(const float4*)&Kt[d * LD_ + tx * 4];
            float ra[4] = {qa.x, qa.y, qa.z, qa.w};
            float rb[4] = {kb.x, kb.y, kb.z, kb.w};
#pragma unroll
            for (int i = 0; i < 4; i++)
#pragma unroll
                for (int j = 0; j < 4; j++)
                    s[i][j] += ra[i] * rb[j];
        }

        const bool diag = (kv0 == q0);
#pragma unroll
        for (int i = 0; i < 4; i++) {
            int qi = ty * 4 + i;
            float4 v;
            float vv[4];
#pragma unroll
            for (int j = 0; j < 4; j++) {
                int kj = tx * 4 + j;
                float sv = s[i][j] * 0.125f;
                if (diag && kj > qi) sv = -1.0e30f;
                vv[j] = sv;
            }
            v.x = vv[0]; v.y = vv[1]; v.z = vv[2]; v.w = vv[3];
            *(float4*)&Ss[qi * LD_ + tx * 4] = v;
        }
        __syncthreads();

        if (tid < 64) {
            const int r = tid;
            const float4* srow = (const float4*)&Ss[r * LD_];
            float mold = m_s[r];
            float mt = mold;
#pragma unroll
            for (int j = 0; j < 16; j++) {
                float4 v = srow[j];
                mt = fmaxf(mt, fmaxf(fmaxf(v.x, v.y), fmaxf(v.z, v.w)));
            }
            float alpha = __expf(mold - mt);
            float sum = 0.f;
#pragma unroll
            for (int j = 0; j < 16; j++) {
                float4 v = srow[j];
                float p0 = __expf(v.x - mt);
                float p1 = __expf(v.y - mt);
                float p2 = __expf(v.z - mt);
                float p3 = __expf(v.w - mt);
                Pt[(4 * j + 0) * LD_ + r] = p0;
                Pt[(4 * j + 1) * LD_ + r] = p1;
                Pt[(4 * j + 2) * LD_ + r] = p2;
                Pt[(4 * j + 3) * LD_ + r] = p3;
                sum += p0 + p1 + p2 + p3;
            }
            m_s[r]  = mt;
            l_s[r]  = l_s[r] * alpha + sum;
            al_s[r] = alpha;
        }
        __syncthreads();

        float a[4];
#pragma unroll
        for (int i = 0; i < 4; i++) a[i] = al_s[ty * 4 + i];
#pragma unroll
        for (int i = 0; i < 4; i++)
#pragma unroll
            for (int j = 0; j < 4; j++) o[i][j] *= a[i];

        for (int kv = 0; kv < 64; kv++) {
            float4 pa = *(const float4*)&Pt[kv * LD_ + ty * 4];
            float4 vb = *(const float4*)&Vs[kv * LD_ + tx * 4];
            float ra[4] = {pa.x, pa.y, pa.z, pa.w};
            float rb[4] = {vb.x, vb.y, vb.z, vb.w};
#pragma unroll
            for (int i = 0; i < 4; i++)
#pragma unroll
                for (int j = 0; j < 4; j++)
                    o[i][j] += ra[i] * rb[j];
        }
    }

    float inv[4];
#pragma unroll
    for (int i = 0; i < 4; i++) inv[i] = 1.0f / l_s[ty * 4 + i];
#pragma unroll
    for (int i = 0; i < 4; i++) {
        float4 v;
        v.x = o[i][0] * inv[i];
        v.y = o[i][1] * inv[i];
        v.z = o[i][2] * inv[i];
        v.w = o[i][3] * inv[i];
        size_t off = (size_t)(b * T_ + q0 + ty * 4 + i) * D_ + h * DK_ + tx * 4;
        *(float4*)(out + off) = v;
    }
}

// ---------------------------------------------------------------------------
extern "C" void kernel_launch(void* const* d_in, const int* in_sizes, int n_in,
                              void* d_out, int out_size)
{
    (void)in_sizes; (void)n_in; (void)out_size;
    const float* x     = (const float*)d_in[0];
    const float* W_qkv = (const float*)d_in[1];
    const float* b_qkv = (const float*)d_in[2];
    const float* W_out = (const float*)d_in[3];
    const float* b_out = (const float*)d_in[4];
    float* out = (float*)d_out;

    float *qkv_ptr, *att_ptr, *wqkvt_ptr, *woutt_ptr;
    cudaGetSymbolAddress((void**)&qkv_ptr,   g_qkv);
    cudaGetSymbolAddress((void**)&att_ptr,   g_att);
    cudaGetSymbolAddress((void**)&wqkvt_ptr, g_wqkv_t);
    cudaGetSymbolAddress((void**)&woutt_ptr, g_wout_t);

    cudaFuncSetAttribute(gemm_tf32_kernel,
                         cudaFuncAttributeMaxDynamicSharedMemorySize, GEMM_SMEM);
    cudaFuncSetAttribute(flash_attn_kernel,
                         cudaFuncAttributeMaxDynamicSharedMemorySize, FLASH_SMEM);

    // 0) Transpose weights to [N, K] K-major
    transpose_kernel<<<dim3(3 * D_ / 32, D_ / 32), 256>>>(W_qkv, wqkvt_ptr, D_, 3 * D_);
    transpose_kernel<<<dim3(D_ / 32, D_ / 32), 256>>>(W_out, woutt_ptr, D_, D_);

    // 1) QKV projection (tf32 mma.sync)
    gemm_tf32_kernel<<<dim3(3 * D_ / 128, M_ / 128), 256, GEMM_SMEM>>>(
        x, wqkvt_ptr, b_qkv, qkv_ptr, M_, 3 * D_, D_);

    // 2) Causal attention (fp32 SIMT)
    flash_attn_kernel<<<dim3(T_ / 64, B_ * H_), 256, FLASH_SMEM>>>(qkv_ptr, att_ptr);

    // 3) Output projection (tf32 mma.sync)
    gemm_tf32_kernel<<<dim3(D_ / 128, M_ / 128), 256, GEMM_SMEM>>>(
        att_ptr, woutt_ptr, b_out, out, M_, D_, D_);
}

// round 4
// speedup vs baseline: 3.0380x; 1.8204x over previous
#include <cuda_runtime.h>
#include <cuda_fp16.h>
#include <cstdint>

#define B_  4
#define T_  2048
#define D_  1024
#define H_  16
#define DK_ 64
#define M_  (B_*T_)
#define BH_ (B_*H_)

// Scratch (allocation-free rule: module-scope device globals)
__device__ float g_qkv[(size_t)M_ * 3 * D_];     // [B,T,3D]
__device__ float g_att[(size_t)M_ * D_];         // [B,T,D]
__device__ float g_wqkv_t[(size_t)3 * D_ * D_];  // W_qkv^T [3D, D]
__device__ float g_wout_t[(size_t)D_ * D_];      // W_out^T [D, D]
// half hi/lo splits for attention
__device__ __half g_q_hi[(size_t)BH_ * T_ * DK_];
__device__ __half g_q_lo[(size_t)BH_ * T_ * DK_];
__device__ __half g_k_hi[(size_t)BH_ * T_ * DK_];
__device__ __half g_k_lo[(size_t)BH_ * T_ * DK_];
__device__ __half g_vt_hi[(size_t)BH_ * DK_ * T_];  // [bh][d][t]
__device__ __half g_vt_lo[(size_t)BH_ * DK_ * T_];

// ---------------------------------------------------------------------------
// PTX helpers
// ---------------------------------------------------------------------------
__device__ __forceinline__ uint32_t smem_u32(const void* p) {
    uint32_t a;
    asm("{ .reg .u64 t; cvta.to.shared.u64 t, %1; cvt.u32.u64 %0, t; }"
        : "=r"(a) : "l"(p));
    return a;
}
__device__ __forceinline__ void cp_async16(uint32_t dst, const void* src) {
    asm volatile("cp.async.ca.shared.global [%0], [%1], 16;"
                 :: "r"(dst), "l"(src) : "memory");
}
__device__ __forceinline__ void cp_commit() {
    asm volatile("cp.async.commit_group;" ::: "memory");
}
__device__ __forceinline__ void cp_wait0() {
    asm volatile("cp.async.wait_group 0;" ::: "memory");
}
__device__ __forceinline__ void cp_wait1() {
    asm volatile("cp.async.wait_group 1;" ::: "memory");
}
__device__ __forceinline__ float ex2f(float x) {
    float y;
    asm("ex2.approx.f32 %0, %1;" : "=f"(y) : "f"(x));
    return y;
}
__device__ __forceinline__ void mma16816(float (&c)[4], uint32_t a0, uint32_t a1,
                                         uint32_t a2, uint32_t a3,
                                         uint32_t b0, uint32_t b1) {
    asm volatile(
        "mma.sync.aligned.m16n8k16.row.col.f32.f16.f16.f32 "
        "{%0,%1,%2,%3}, {%4,%5,%6,%7}, {%8,%9}, {%0,%1,%2,%3};"
        : "+f"(c[0]), "+f"(c[1]), "+f"(c[2]), "+f"(c[3])
        : "r"(a0), "r"(a1), "r"(a2), "r"(a3), "r"(b0), "r"(b1));
}

// ---------------------------------------------------------------------------
// Transpose: out[c][r] = in[r][c]   (in: [R,C])
// ---------------------------------------------------------------------------
__global__ __launch_bounds__(256)
void transpose_kernel(const float* __restrict__ in, float* __restrict__ out,
                      int R, int C)
{
    __shared__ float t[32][33];
    int bx = blockIdx.x * 32;
    int by = blockIdx.y * 32;
    int tx = threadIdx.x & 31, ty = threadIdx.x >> 5;
#pragma unroll
    for (int j = 0; j < 32; j += 8)
        t[ty + j][tx] = in[(size_t)(by + ty + j) * C + bx + tx];
    __syncthreads();
#pragma unroll
    for (int j = 0; j < 32; j += 8)
        out[(size_t)(bx + ty + j) * R + by + tx] = t[tx][ty + j];
}

// ---------------------------------------------------------------------------
// tf32 mma.sync GEMM (unchanged from round 3, passes @ 5.5e-4)
// ---------------------------------------------------------------------------
#define APAD   20
#define TILE_B (128 * APAD * 4)
#define STAGE_B (2 * TILE_B)
#define GEMM_SMEM (2 * STAGE_B)

__device__ __forceinline__ void cvt4_rna(uint32_t (&o)[4], float4 v) {
    asm("cvt.rna.tf32.f32 %0, %1;" : "=r"(o[0]) : "f"(v.x));
    asm("cvt.rna.tf32.f32 %0, %1;" : "=r"(o[1]) : "f"(v.y));
    asm("cvt.rna.tf32.f32 %0, %1;" : "=r"(o[2]) : "f"(v.z));
    asm("cvt.rna.tf32.f32 %0, %1;" : "=r"(o[3]) : "f"(v.w));
}
__device__ __forceinline__ void mma_tf32(float (&c)[4], const uint32_t (&a)[4],
                                         const uint32_t (&b)[2]) {
    asm volatile(
        "mma.sync.aligned.m16n8k8.row.col.f32.tf32.tf32.f32 "
        "{%0,%1,%2,%3}, {%4,%5,%6,%7}, {%8,%9}, {%0,%1,%2,%3};"
        : "+f"(c[0]), "+f"(c[1]), "+f"(c[2]), "+f"(c[3])
        : "r"(a[0]), "r"(a[1]), "r"(a[2]), "r"(a[3]), "r"(b[0]), "r"(b[1]));
}

__global__ __launch_bounds__(256, 2)
void gemm_tf32_kernel(const float* __restrict__ A,
                      const float* __restrict__ Bt,
                      const float* __restrict__ bias,
                      float* __restrict__ C,
                      int M, int N, int K)
{
    extern __shared__ char smem[];
    const int tid  = threadIdx.x;
    const int wid  = tid >> 5;
    const int lane = tid & 31;
    const int grp  = lane >> 2;
    const int tg   = lane & 3;
    const int warp_m = (wid & 1) * 64;
    const int warp_n = (wid >> 1) * 32;
    const int m0 = blockIdx.y * 128;
    const int n0 = blockIdx.x * 128;
    const int nk = K >> 4;

    const int r0 = (tid) >> 2,        kc0 = ((tid) & 3) << 2;
    const int r1 = (tid + 256) >> 2,  kc1 = ((tid + 256) & 3) << 2;

    const float* Abase = A + (size_t)m0 * K;
    const float* Bbase = Bt + (size_t)n0 * K;

    float acc[4][4][4];
#pragma unroll
    for (int i = 0; i < 4; i++)
#pragma unroll
        for (int j = 0; j < 4; j++)
#pragma unroll
            for (int r = 0; r < 4; r++) acc[i][j][r] = 0.f;

    float4 ra0, ra1, rb0, rb1;
    ra0 = *(const float4*)(Abase + (size_t)r0 * K + kc0);
    ra1 = *(const float4*)(Abase + (size_t)r1 * K + kc1);
    rb0 = *(const float4*)(Bbase + (size_t)r0 * K + kc0);
    rb1 = *(const float4*)(Bbase + (size_t)r1 * K + kc1);

    for (int i = 0; i < nk; i++) {
        float* As = (float*)(smem + (i & 1) * STAGE_B);
        float* Bs = (float*)(smem + (i & 1) * STAGE_B + TILE_B);
        {
            uint32_t c4[4];
            cvt4_rna(c4, ra0); *(uint4*)(As + r0 * APAD + kc0) = *(uint4*)c4;
            cvt4_rna(c4, ra1); *(uint4*)(As + r1 * APAD + kc1) = *(uint4*)c4;
            cvt4_rna(c4, rb0); *(uint4*)(Bs + r0 * APAD + kc0) = *(uint4*)c4;
            cvt4_rna(c4, rb1); *(uint4*)(Bs + r1 * APAD + kc1) = *(uint4*)c4;
        }
        __syncthreads();

        if (i + 1 < nk) {
            const int k0 = (i + 1) << 4;
            ra0 = *(const float4*)(Abase + (size_t)r0 * K + k0 + kc0);
            ra1 = *(const float4*)(Abase + (size_t)r1 * K + k0 + kc1);
            rb0 = *(const float4*)(Bbase + (size_t)r0 * K + k0 + kc0);
            rb1 = *(const float4*)(Bbase + (size_t)r1 * K + k0 + kc1);
        }

        const uint32_t* Au = (const uint32_t*)As;
        const uint32_t* Bu = (const uint32_t*)Bs;
#pragma unroll
        for (int ks = 0; ks < 2; ks++) {
            const int k0 = ks * 8 + tg;
            uint32_t a[4][4];
#pragma unroll
            for (int ii = 0; ii < 4; ii++) {
                const uint32_t* p0 = Au + (warp_m + 16 * ii + grp) * APAD;
                a[ii][0] = p0[k0];
                a[ii][2] = p0[k0 + 4];
                const uint32_t* p1 = p0 + 8 * APAD;
                a[ii][1] = p1[k0];
                a[ii][3] = p1[k0 + 4];
            }
            uint32_t b[4][2];
#pragma unroll
            for (int jj = 0; jj < 4; jj++) {
                const uint32_t* pn = Bu + (warp_n + 8 * jj + grp) * APAD;
                b[jj][0] = pn[k0];
                b[jj][1] = pn[k0 + 4];
            }
#pragma unroll
            for (int ii = 0; ii < 4; ii++)
#pragma unroll
                for (int jj = 0; jj < 4; jj++)
                    mma_tf32(acc[ii][jj], a[ii], b[jj]);
        }
    }

#pragma unroll
    for (int ii = 0; ii < 4; ii++) {
        const int m = m0 + warp_m + 16 * ii + grp;
#pragma unroll
        for (int jj = 0; jj < 4; jj++) {
            const int n = n0 + warp_n + 8 * jj + 2 * tg;
            const float bv0 = __ldg(&bias[n]);
            const float bv1 = __ldg(&bias[n + 1]);
            float2 v0 = {acc[ii][jj][0] + bv0, acc[ii][jj][1] + bv1};
            float2 v1 = {acc[ii][jj][2] + bv0, acc[ii][jj][3] + bv1};
            *(float2*)(C + (size_t)m * N + n)       = v0;
            *(float2*)(C + (size_t)(m + 8) * N + n) = v1;
        }
    }
}

// ---------------------------------------------------------------------------
// Pre-pass 1: split Q,K from g_qkv into half hi/lo, layout [bh][t][64]
// ---------------------------------------------------------------------------
__device__ __forceinline__ void split_store4(float4 v, __half* hi, __half* lo,
                                             size_t o) {
    __half2 h0 = __floats2half2_rn(v.x, v.y);
    __half2 h1 = __floats2half2_rn(v.z, v.w);
    float2 f0 = __half22float2(h0), f1 = __half22float2(h1);
    __half2 l0 = __floats2half2_rn(v.x - f0.x, v.y - f0.y);
    __half2 l1 = __floats2half2_rn(v.z - f1.x, v.w - f1.y);
    *(__half2*)(hi + o)     = h0;
    *(__half2*)(hi + o + 2) = h1;
    *(__half2*)(lo + o)     = l0;
    *(__half2*)(lo + o + 2) = l1;
}

__global__ __launch_bounds__(256)
void convert_qk_kernel(const float* __restrict__ qkv,
                       __half* __restrict__ qh, __half* __restrict__ ql,
                       __half* __restrict__ kh, __half* __restrict__ kl)
{
    int i = blockIdx.x * 256 + threadIdx.x;       // < BH*T*16
    int c4 = i & 15;
    int t  = (i >> 4) & (T_ - 1);
    int bh = i >> 15;
    int b = bh >> 4, h = bh & 15;
    const float4* src = (const float4*)(qkv + ((size_t)(b * T_ + t)) * 3 * D_);
    float4 q4 = src[h * 16 + c4];
    float4 k4 = src[256 + h * 16 + c4];
    size_t o = ((size_t)bh * T_ + t) * 64 + c4 * 4;
    split_store4(q4, qh, ql, o);
    split_store4(k4, kh, kl, o);
}

// ---------------------------------------------------------------------------
// Pre-pass 2: V transpose + split: g_qkv V part -> [bh][d][t] hi/lo halfs
// ---------------------------------------------------------------------------
__global__ __launch_bounds__(256)
void convert_vt_kernel(const float* __restrict__ qkv,
                       __half* __restrict__ vh, __half* __restrict__ vl)
{
    __shared__ float tile[32][33];
    int t0 = blockIdx.x * 32;
    int d0 = blockIdx.y * 32;
    int bh = blockIdx.z;
    int b = bh >> 4, h = bh & 15;
    int tx = threadIdx.x & 31, ty = threadIdx.x >> 5;
#pragma unroll
    for (int j = 0; j < 32; j += 8)
        tile[ty + j][tx] = qkv[((size_t)(b * T_ + t0 + ty + j)) * 3 * D_
                               + 2 * D_ + h * 64 + d0 + tx];
    __syncthreads();
#pragma unroll
    for (int j = 0; j < 32; j += 8) {
        int d = d0 + ty + j;
        float v = tile[tx][ty + j];
        __half hv = __float2half_rn(v);
        __half lv = __float2half_rn(v - __half2float(hv));
        size_t o = ((size_t)bh * DK_ + d) * T_ + t0 + tx;
        vh[o] = hv;
        vl[o] = lv;
    }
}

// ---------------------------------------------------------------------------
// Flash attention on fp16 tensor cores with hi/lo split (near-fp32 accuracy).
// CTA: 256 thr (8 warps), q-tile 128 (warp = 16 rows), kv-tile 64, DK 64.
// Smem (words): double-buffered [2][Kh|Kl|Vh|Vl], each 64*AW; Q staged in buf
// region once at start. AW=36 -> all fragment LDS conflict-free (4*grp+tg).
// ---------------------------------------------------------------------------
#define AW   36
#define KVW  (64 * AW)               // 2304 words per array
#define BUFW (4 * KVW)               // 9216 words per stage
#define ATT_SMEM (2 * BUFW * 4)      // 73728 bytes

__global__ __launch_bounds__(256, 2)
void flash_mma_kernel(const __half* __restrict__ qh_g, const __half* __restrict__ ql_g,
                      const __half* __restrict__ kh_g, const __half* __restrict__ kl_g,
                      const __half* __restrict__ vh_g, const __half* __restrict__ vl_g,
                      float* __restrict__ out)
{
    extern __shared__ uint32_t smw[];
    const uint32_t sbase = smem_u32(smw);
    const int tid = threadIdx.x, wid = tid >> 5, lane = tid & 31;
    const int grp = lane >> 2, tg = lane & 3;
    const int bh = blockIdx.y, b = bh >> 4, h = bh & 15;
    const int qt = gridDim.x - 1 - blockIdx.x;        // heavy CTAs first
    const int q0 = qt * 128;
    const int wm = wid * 16;
    const int row0 = q0 + wm + grp;
    const int row1 = row0 + 8;

    // ---- stage Q (hi|lo) into smem buf region, then lift fragments to regs
    {
        const uint4* qh4 = (const uint4*)(qh_g + (size_t)bh * T_ * DK_) + q0 * 8;
        const uint4* ql4 = (const uint4*)(ql_g + (size_t)bh * T_ * DK_) + q0 * 8;
#pragma unroll
        for (int j = 0; j < 4; j++) {
            int idx = tid + j * 256;           // 1024 uint4 per array
            int r = idx >> 3, c = idx & 7;
            uint32_t dst = sbase + (r * AW + c * 4) * 4;
            cp_async16(dst, qh4 + r * 8 + c);
            cp_async16(dst + 4608 * 4, ql4 + r * 8 + c);
        }
        cp_commit(); cp_wait0();
        __syncthreads();
    }
    uint32_t qfh[4][4], qfl[4][4];
    {
        const uint32_t* Q = smw;
        const int base = (wm + grp) * AW + tg;
#pragma unroll
        for (int kc = 0; kc < 4; kc++) {
            qfh[kc][0] = Q[base + 8 * kc];
            qfh[kc][1] = Q[base + 8 * AW + 8 * kc];
            qfh[kc][2] = Q[base + 8 * kc + 4];
            qfh[kc][3] = Q[base + 8 * AW + 8 * kc + 4];
            qfl[kc][0] = Q[4608 + base + 8 * kc];
            qfl[kc][1] = Q[4608 + base + 8 * AW + 8 * kc];
            qfl[kc][2] = Q[4608 + base + 8 * kc + 4];
            qfl[kc][3] = Q[4608 + base + 8 * AW + 8 * kc + 4];
        }
    }
    __syncthreads();    // Q staging region becomes KV buffer 0

    const uint4* kh4 = (const uint4*)(kh_g + (size_t)bh * T_ * DK_);
    const uint4* kl4 = (const uint4*)(kl_g + (size_t)bh * T_ * DK_);
    const uint4* vh4 = (const uint4*)(vh_g + (size_t)bh * DK_ * T_);
    const uint4* vl4 = (const uint4*)(vl_g + (size_t)bh * DK_ * T_);

    auto kv_load = [&](int t, int buf) {
        const int kv0 = t * 64;
#pragma unroll
        for (int j = 0; j < 2; j++) {
            int idx = tid + j * 256;           // 512 uint4 per array
            int r = idx >> 3, c = idx & 7;
            uint32_t dst = sbase + (buf * BUFW + r * AW + c * 4) * 4;
            cp_async16(dst,                kh4 + (kv0 + r) * 8 + c);
            cp_async16(dst + KVW * 4,      kl4 + (kv0 + r) * 8 + c);
            cp_async16(dst + 2 * KVW * 4,  vh4 + (size_t)r * (T_ / 8) + kv0 / 8 + c);
            cp_async16(dst + 3 * KVW * 4,  vl4 + (size_t)r * (T_ / 8) + kv0 / 8 + c);
        }
    };

    float o[8][4];
#pragma unroll
    for (int j = 0; j < 8; j++)
#pragma unroll
        for (int e = 0; e < 4; e++) o[j][e] = 0.f;
    float m0 = -1e30f, m1 = -1e30f, l0 = 0.f, l1 = 0.f;

    const int nt = 2 * (qt + 1);
    kv_load(0, 0); cp_commit();

    for (int t = 0; t < nt; t++) {
        if (t + 1 < nt) { kv_load(t + 1, (t + 1) & 1); cp_commit(); cp_wait1(); }
        else           { cp_wait0(); }
        __syncthreads();

        const uint32_t* Kh = smw + (t & 1) * BUFW;
        const uint32_t* Kl = Kh + KVW;
        const uint32_t* Vh = Kh + 2 * KVW;
        const uint32_t* Vl = Kh + 3 * KVW;

        // ---- S = Q @ K^T (3-term split fp16)
        float s[8][4];
#pragma unroll
        for (int j = 0; j < 8; j++)
#pragma unroll
            for (int e = 0; e < 4; e++) s[j][e] = 0.f;
#pragma unroll
        for (int kc = 0; kc < 4; kc++) {
            const int bo = 8 * kc + tg;
#pragma unroll
            for (int j = 0; j < 8; j++) {
                const int nb = (8 * j + grp) * AW + bo;
                uint32_t b0h = Kh[nb], b1h = Kh[nb + 4];
                uint32_t b0l = Kl[nb], b1l = Kl[nb + 4];
                mma16816(s[j], qfh[kc][0], qfh[kc][1], qfh[kc][2], qfh[kc][3], b0h, b1h);
                mma16816(s[j], qfl[kc][0], qfl[kc][1], qfl[kc][2], qfl[kc][3], b0h, b1h);
                mma16816(s[j], qfh[kc][0], qfh[kc][1], qfh[kc][2], qfh[kc][3], b0l, b1l);
            }
        }

        // ---- online softmax (base-2, scale folded)
        const int kv0 = t * 64;
        const float cs = 0.125f * 1.4426950408889634f;
        const bool maskw = (kv0 + 63 > q0 + wm);
        float mx0 = -1e30f, mx1 = -1e30f;
#pragma unroll
        for (int j = 0; j < 8; j++) {
            const int c0 = kv0 + 8 * j + 2 * tg;
            float x0 = s[j][0] * cs, x1 = s[j][1] * cs;
            float x2 = s[j][2] * cs, x3 = s[j][3] * cs;
            if (maskw) {
                if (c0 > row0)     x0 = -1e30f;
                if (c0 + 1 > row0) x1 = -1e30f;
                if (c0 > row1)     x2 = -1e30f;
                if (c0 + 1 > row1) x3 = -1e30f;
            }
            s[j][0] = x0; s[j][1] = x1; s[j][2] = x2; s[j][3] = x3;
            mx0 = fmaxf(mx0, fmaxf(x0, x1));
            mx1 = fmaxf(mx1, fmaxf(x2, x3));
        }
        mx0 = fmaxf(mx0, __shfl_xor_sync(0xffffffffu, mx0, 1));
        mx0 = fmaxf(mx0, __shfl_xor_sync(0xffffffffu, mx0, 2));
        mx1 = fmaxf(mx1, __shfl_xor_sync(0xffffffffu, mx1, 1));
        mx1 = fmaxf(mx1, __shfl_xor_sync(0xffffffffu, mx1, 2));
        const float mn0 = fmaxf(m0, mx0), mn1 = fmaxf(m1, mx1);
        const float a0 = ex2f(m0 - mn0),  a1 = ex2f(m1 - mn1);
        m0 = mn0; m1 = mn1;

        float sum0 = 0.f, sum1 = 0.f;
#pragma unroll
        for (int j = 0; j < 8; j++) {
            float p0 = ex2f(s[j][0] - m0), p1 = ex2f(s[j][1] - m0);
            float p2 = ex2f(s[j][2] - m1), p3 = ex2f(s[j][3] - m1);
            s[j][0] = p0; s[j][1] = p1; s[j][2] = p2; s[j][3] = p3;
            sum0 += p0 + p1; sum1 += p2 + p3;
        }
        sum0 += __shfl_xor_sync(0xffffffffu, sum0, 1);
        sum0 += __shfl_xor_sync(0xffffffffu, sum0, 2);
        sum1 += __shfl_xor_sync(0xffffffffu, sum1, 1);
        sum1 += __shfl_xor_sync(0xffffffffu, sum1, 2);
        l0 = l0 * a0 + sum0;
        l1 = l1 * a1 + sum1;
#pragma unroll
        for (int j = 0; j < 8; j++) {
            o[j][0] *= a0; o[j][1] *= a0; o[j][2] *= a1; o[j][3] *= a1;
        }

        // ---- O += P @ V (3-term split fp16; P frags直接 from S accumulators)
#pragma unroll
        for (int kc = 0; kc < 4; kc++) {
            const int j0 = 2 * kc, j1 = 2 * kc + 1;
            __half2 A0 = __floats2half2_rn(s[j0][0], s[j0][1]);
            __half2 A1 = __floats2half2_rn(s[j0][2], s[j0][3]);
            __half2 A2 = __floats2half2_rn(s[j1][0], s[j1][1]);
            __half2 A3 = __floats2half2_rn(s[j1][2], s[j1][3]);
            float2 f0 = __half22float2(A0), f1 = __half22float2(A1);
            float2 f2 = __half22float2(A2), f3 = __half22float2(A3);
            __half2 L0 = __floats2half2_rn(s[j0][0] - f0.x, s[j0][1] - f0.y);
            __half2 L1 = __floats2half2_rn(s[j0][2] - f1.x, s[j0][3] - f1.y);
            __half2 L2 = __floats2half2_rn(s[j1][0] - f2.x, s[j1][1] - f2.y);
            __half2 L3 = __floats2half2_rn(s[j1][2] - f3.x, s[j1][3] - f3.y);
            const uint32_t ph0 = *(uint32_t*)&A0, ph1 = *(uint32_t*)&A1;
            const uint32_t ph2 = *(uint32_t*)&A2, ph3 = *(uint32_t*)&A3;
            const uint32_t pl0 = *(uint32_t*)&L0, pl1 = *(uint32_t*)&L1;
            const uint32_t pl2 = *(uint32_t*)&L2, pl3 = *(uint32_t*)&L3;
            const int bo = 8 * kc + tg;
#pragma unroll
            for (int jj = 0; jj < 8; jj++) {
                const int nb = (8 * jj + grp) * AW + bo;
                uint32_t v0h = Vh[nb], v1h = Vh[nb + 4];
                uint32_t v0l = Vl[nb], v1l = Vl[nb + 4];
                mma16816(o[jj], ph0, ph1, ph2, ph3, v0h, v1h);
                mma16816(o[jj], pl0, pl1, pl2, pl3, v0h, v1h);
                mma16816(o[jj], ph0, ph1, ph2, ph3, v0l, v1l);
            }
        }
        __syncthreads();
    }

    // ---- epilogue
    const float i0 = 1.0f / l0, i1 = 1.0f / l1;
    float* out0 = out + ((size_t)(b * T_ + row0)) * D_ + h * 64 + 2 * tg;
    float* out1 = out + ((size_t)(b * T_ + row1)) * D_ + h * 64 + 2 * tg;
#pragma unroll
    for (int jj = 0; jj < 8; jj++) {
        float2 v0 = {o[jj][0] * i0, o[jj][1] * i0};
        float2 v1 = {o[jj][2] * i1, o[jj][3] * i1};
        *(float2*)(out0 + 8 * jj) = v0;
        *(float2*)(out1 + 8 * jj) = v1;
    }
}

// ---------------------------------------------------------------------------
extern "C" void kernel_launch(void* const* d_in, const int* in_sizes, int n_in,
                              void* d_out, int out_size)
{
    (void)in_sizes; (void)n_in; (void)out_size;
    const float* x     = (const float*)d_in[0];
    const float* W_qkv = (const float*)d_in[1];
    const float* b_qkv = (const float*)d_in[2];
    const float* W_out = (const float*)d_in[3];
    const float* b_out = (const float*)d_in[4];
    float* out = (float*)d_out;

    float *qkv_ptr, *att_ptr, *wqkvt_ptr, *woutt_ptr;
    cudaGetSymbolAddress((void**)&qkv_ptr,   g_qkv);
    cudaGetSymbolAddress((void**)&att_ptr,   g_att);
    cudaGetSymbolAddress((void**)&wqkvt_ptr, g_wqkv_t);
    cudaGetSymbolAddress((void**)&woutt_ptr, g_wout_t);
    __half *qh, *ql, *kh, *kl, *vh, *vl;
    cudaGetSymbolAddress((void**)&qh, g_q_hi);
    cudaGetSymbolAddress((void**)&ql, g_q_lo);
    cudaGetSymbolAddress((void**)&kh, g_k_hi);
    cudaGetSymbolAddress((void**)&kl, g_k_lo);
    cudaGetSymbolAddress((void**)&vh, g_vt_hi);
    cudaGetSymbolAddress((void**)&vl, g_vt_lo);

    cudaFuncSetAttribute(gemm_tf32_kernel,
                         cudaFuncAttributeMaxDynamicSharedMemorySize, GEMM_SMEM);
    cudaFuncSetAttribute(flash_mma_kernel,
                         cudaFuncAttributeMaxDynamicSharedMemorySize, ATT_SMEM);

    // 0) Transpose weights to [N, K]
    transpose_kernel<<<dim3(3 * D_ / 32, D_ / 32), 256>>>(W_qkv, wqkvt_ptr, D_, 3 * D_);
    transpose_kernel<<<dim3(D_ / 32, D_ / 32), 256>>>(W_out, woutt_ptr, D_, D_);

    // 1) QKV projection (tf32 mma)
    gemm_tf32_kernel<<<dim3(3 * D_ / 128, M_ / 128), 256, GEMM_SMEM>>>(
        x, wqkvt_ptr, b_qkv, qkv_ptr, M_, 3 * D_, D_);

    // 2) Split/transpose Q,K,V to half hi/lo
    convert_qk_kernel<<<(BH_ * T_ * 16) / 256, 256>>>(qkv_ptr, qh, ql, kh, kl);
    convert_vt_kernel<<<dim3(T_ / 32, DK_ / 32, BH_), 256>>>(qkv_ptr, vh, vl);

    // 3) Causal attention (fp16 mma, split-3x accuracy)
    flash_mma_kernel<<<dim3(T_ / 128, BH_), 256, ATT_SMEM>>>(
        qh, ql, kh, kl, vh, vl, att_ptr);

    // 4) Output projection (tf32 mma)
    gemm_tf32_kernel<<<dim3(D_ / 128, M_ / 128), 256, GEMM_SMEM>>>(
        att_ptr, woutt_ptr, b_out, out, M_, D_, D_);
}